// round 12
// baseline (speedup 1.0000x reference)
#include <cuda_runtime.h>
#include <cuda_fp16.h>
#include <math.h>
#include <cstdint>

#define N_SRC 32768
#define M_TGT 8192
#define D_DIM 64
#define REG_P 0.01f
#define INV_REG 100.0f
#define LOG2E 1.4426950408889634f
#define LN2 0.6931471805599453f

#define BM 128
#define BN 64
#define NT 256
#define NCPSM 3
#define GRID (148 * NCPSM)      // 444
#define NRB (N_SRC / BM)        // 256 row-blocks
#define NCHUNK 8
#define TPC 16                  // 64-row tiles per chunk
#define NJOBS (NRB * NCHUNK)    // 2048
#define NSTAGE 4

// ---------------- scratch ----------------
__device__ float    g_tysq[M_TGT];
__device__ uint32_t g_ch2[M_TGT];    // half2(c2hi, c2lo), c2 = (psi - tysq/mv)*INV_REG*LOG2E
__device__ float    g_scalars[4];    // 0: 1/mv, 1: 2*invmv*INV_REG*LOG2E, 2: mean(psi)
__device__ __half   g_Xh[N_SRC * D_DIM];   // pre-scaled by s2
__device__ __half   g_Yh[M_TGT * D_DIM];
__device__ float    g_pm[NRB * NCHUNK * 2 * BM];
__device__ float    g_ps[NRB * NCHUNK * 2 * BM];
__device__ int      g_job;

// ---------------- helpers ----------------
__device__ __forceinline__ uint32_t smem_u32(const void* p) {
    uint32_t a;
    asm("{ .reg .u64 t; cvta.to.shared.u64 t, %1; cvt.u32.u64 %0, t; }" : "=r"(a) : "l"(p));
    return a;
}
__device__ __forceinline__ uint64_t gmem_u64(const void* p) {
    uint64_t a;
    asm("cvta.to.global.u64 %0, %1;" : "=l"(a) : "l"(p));
    return a;
}
__device__ __forceinline__ float ex2f(float x) {
    float r; asm("ex2.approx.ftz.f32 %0, %1;" : "=f"(r) : "f"(x)); return r;
}
__device__ __forceinline__ float lg2f(float x) {
    float r; asm("lg2.approx.f32 %0, %1;" : "=f"(r) : "f"(x)); return r;
}

#define CP_ASYNC16(s, g) \
    asm volatile("cp.async.cg.shared.global [%0], [%1], 16;" :: "r"(s), "l"(g))
#define CP_COMMIT() asm volatile("cp.async.commit_group;" ::: "memory")
#define CP_WAIT(n)  asm volatile("cp.async.wait_group %0;" :: "n"(n) : "memory")

__device__ __forceinline__ void ldsm4(uint32_t* r, uint32_t addr) {
    asm volatile("ldmatrix.sync.aligned.m8n8.x4.shared.b16 {%0,%1,%2,%3}, [%4];"
                 : "=r"(r[0]), "=r"(r[1]), "=r"(r[2]), "=r"(r[3]) : "r"(addr));
}
__device__ __forceinline__ void mma_f16(float* c, const uint32_t* a,
                                        uint32_t b0, uint32_t b1) {
    asm volatile("mma.sync.aligned.m16n8k16.row.col.f32.f16.f16.f32 "
                 "{%0,%1,%2,%3}, {%4,%5,%6,%7}, {%8,%9}, {%0,%1,%2,%3};"
                 : "+f"(c[0]), "+f"(c[1]), "+f"(c[2]), "+f"(c[3])
                 : "r"(a[0]), "r"(a[1]), "r"(a[2]), "r"(a[3]), "r"(b0), "r"(b1));
}

// smem layout (bytes): Xh 16KB | Yh 4x8KB | ch2 4x256B
#define SM_X 0
#define SM_Y 16384
#define SM_C (16384 + NSTAGE * 8192)
#define SM_TOTAL (SM_C + NSTAGE * 256 + 128)

// ---------------- prologue kernels ----------------
__global__ void convY_tysq_kernel(const float* __restrict__ Y) {
    int gid = blockIdx.x * blockDim.x + threadIdx.x;
    int r = gid >> 3, c8 = gid & 7;
    const float4* p = reinterpret_cast<const float4*>(Y + (size_t)r * D_DIM + c8 * 8);
    float4 v0 = p[0], v1 = p[1];
    __half2 h[4];
    h[0] = __float22half2_rn(make_float2(v0.x, v0.y));
    h[1] = __float22half2_rn(make_float2(v0.z, v0.w));
    h[2] = __float22half2_rn(make_float2(v1.x, v1.y));
    h[3] = __float22half2_rn(make_float2(v1.z, v1.w));
    *reinterpret_cast<uint4*>(g_Yh + (size_t)r * D_DIM + c8 * 8) =
        *reinterpret_cast<uint4*>(h);
    float s = v0.x * v0.x + v0.y * v0.y + v0.z * v0.z + v0.w * v0.w
            + v1.x * v1.x + v1.y * v1.y + v1.z * v1.z + v1.w * v1.w;
    s += __shfl_down_sync(0xffffffffu, s, 4, 8);
    s += __shfl_down_sync(0xffffffffu, s, 2, 8);
    s += __shfl_down_sync(0xffffffffu, s, 1, 8);
    if (c8 == 0) g_tysq[r] = s;
}

__global__ void prep_kernel(const float* __restrict__ psi) {
    __shared__ float red_t[1024];
    __shared__ float red_p[1024];
    __shared__ float inv_mv_s;
    int t = threadIdx.x;
    float st = 0.f, sp = 0.f;
    for (int m = t; m < M_TGT; m += 1024) { st += g_tysq[m]; sp += psi[m]; }
    red_t[t] = st; red_p[t] = sp;
    __syncthreads();
    for (int off = 512; off > 0; off >>= 1) {
        if (t < off) { red_t[t] += red_t[t + off]; red_p[t] += red_p[t + off]; }
        __syncthreads();
    }
    if (t == 0) {
        float mv = red_t[0] / (float)M_TGT;
        float inv_mv = 1.0f / mv;
        g_scalars[0] = inv_mv;
        g_scalars[1] = 2.0f * inv_mv * INV_REG * LOG2E;
        g_scalars[2] = red_p[0] / (float)M_TGT;
        inv_mv_s = inv_mv;
        g_job = GRID;
    }
    __syncthreads();
    float inv_mv = inv_mv_s;
    for (int m = t; m < M_TGT; m += 1024) {
        float c2 = (psi[m] - g_tysq[m] * inv_mv) * (INV_REG * LOG2E);
        __half hi = __float2half_rn(c2);
        __half lo = __float2half_rn(c2 - __half2float(hi));
        __half2 pk = __halves2half2(hi, lo);     // lo half = hi-part (k even)
        g_ch2[m] = *reinterpret_cast<uint32_t*>(&pk);
    }
}

// X conversion AFTER prep: xh = rn(s2 * x)
__global__ void convX_kernel(const float* __restrict__ src) {
    int i = blockIdx.x * blockDim.x + threadIdx.x;
    if (i >= N_SRC * D_DIM / 2) return;
    float s2 = g_scalars[1];
    float2 v = reinterpret_cast<const float2*>(src)[i];
    reinterpret_cast<__half2*>(g_Xh)[i] =
        __float22half2_rn(make_float2(s2 * v.x, s2 * v.y));
}

// ---------------- main kernel ----------------
extern __shared__ char smem[];

__global__ __launch_bounds__(NT, NCPSM)
void lse_mma_kernel() {
    __shared__ int job_s;
    const uint32_t sb = smem_u32(smem);
    const int tid  = threadIdx.x;
    const int lane = tid & 31;
    const int wid  = tid >> 5;
    const int mwarp = wid >> 1;          // 0..3 -> rows mwarp*32..+31
    const int nwarp = wid & 1;           // 0..1 -> cols nwarp*32..+31
    const int q  = lane & 3;
    const int g4 = lane >> 2;

    const uint64_t Yg = gmem_u64(g_Yh);
    const uint64_t Cg = gmem_u64(g_ch2);

    const int b = lane >> 3, lr = lane & 7;
    const int rselA = (b & 1) * 8, cselA = b >> 1;
    const int rselB = (b >> 1) * 8, cselB = b & 1;

    // constant A fragment for the c-fold step: (1,1) at k0,k1, lanes q==0
    const uint32_t ae = (q == 0) ? 0x3C003C00u : 0u;
    const uint32_t Aext[4] = {ae, ae, 0u, 0u};

    // hoisted per-thread prefetch offsets (Y tile = 512 x 16B chunks)
    uint32_t og[2], os[2];
#pragma unroll
    for (int i = 0; i < 2; i++) {
        int idx = tid + i * NT;
        int row = idx >> 3, ch = idx & 7;
        og[i] = (uint32_t)(row * 128 + ch * 16);
        os[i] = (uint32_t)(row * 128 + ((ch ^ (row & 7)) << 4));
    }

    int job = blockIdx.x;
    while (job < NJOBS) {
        const int rb = job >> 3;
        const int ck = job & 7;
        const int rowBase = rb * BM;
        const int tile0 = ck * TPC;

        // ---- X tile (fp16, pre-scaled) -> smem ----
#pragma unroll
        for (int i = 0; i < 4; i++) {
            int idx = tid + i * NT;
            int row = idx >> 3, ch = idx & 7;
            uint4 v = *reinterpret_cast<const uint4*>(
                reinterpret_cast<const char*>(g_Xh) +
                (uint64_t)(rowBase + row) * 128 + ch * 16);
            *reinterpret_cast<uint4*>(smem + SM_X + row * 128 +
                                      ((ch ^ (row & 7)) << 4)) = v;
        }
        // ---- prefetch Y tiles 0..2 ----
#pragma unroll
        for (int pt = 0; pt < NSTAGE - 1; pt++) {
            uint64_t gb = Yg + (uint64_t)(tile0 + pt) * 8192;
            uint32_t sbase = sb + SM_Y + pt * 8192;
            CP_ASYNC16(sbase + os[0], gb + og[0]);
            CP_ASYNC16(sbase + os[1], gb + og[1]);
            if (tid < 16)
                CP_ASYNC16(sb + SM_C + pt * 256 + tid * 16,
                           Cg + (uint64_t)(tile0 + pt) * 256 + tid * 16);
            CP_COMMIT();
        }
        __syncthreads();

        // ---- A fragments (persistent for the job) ----
        uint32_t A[2][4][4];
#pragma unroll
        for (int mt = 0; mt < 2; mt++)
#pragma unroll
            for (int ks = 0; ks < 4; ks++) {
                int row = mwarp * 32 + mt * 16 + rselA + lr;
                int ch  = ks * 2 + cselA;
                ldsm4(A[mt][ks], sb + SM_X + row * 128 + ((ch ^ lr) << 4));
            }

        float runm[4], runs[4];
#pragma unroll
        for (int r = 0; r < 4; r++) { runm[r] = -INFINITY; runs[r] = 0.f; }

        for (int t = 0; t < TPC; t++) {
            CP_WAIT(2);
            __syncthreads();
            const int buf = t & (NSTAGE - 1);
            const uint32_t yb = sb + SM_Y + buf * 8192;

            if (t + NSTAGE - 1 < TPC) {
                const int stg = (t + NSTAGE - 1) & (NSTAGE - 1);
                uint64_t gb = Yg + (uint64_t)(tile0 + t + NSTAGE - 1) * 8192;
                uint32_t sbase = sb + SM_Y + stg * 8192;
                CP_ASYNC16(sbase + os[0], gb + og[0]);
                CP_ASYNC16(sbase + os[1], gb + og[1]);
                if (tid < 16)
                    CP_ASYNC16(sb + SM_C + stg * 256 + tid * 16,
                               Cg + (uint64_t)(tile0 + t + NSTAGE - 1) * 256 + tid * 16);
            }
            CP_COMMIT();

            const uint32_t* ch2s =
                reinterpret_cast<const uint32_t*>(smem + SM_C + buf * 256);

#pragma unroll
            for (int nt2 = 0; nt2 < 2; nt2++) {
                const int nbase = nwarp * 32 + nt2 * 16;
                const uint32_t rowb = yb + (uint32_t)(nbase + rselB + lr) * 128;
                // c-fold B fragments (only q==0 lanes carry data)
                uint32_t e0 = ch2s[nbase + g4];
                uint32_t e1 = ch2s[nbase + 8 + g4];
                e0 = (q == 0) ? e0 : 0u;
                e1 = (q == 0) ? e1 : 0u;

                float acc[2][2][4];
#pragma unroll
                for (int mt = 0; mt < 2; mt++)
#pragma unroll
                    for (int nf = 0; nf < 2; nf++)
#pragma unroll
                        for (int j = 0; j < 4; j++) acc[mt][nf][j] = 0.f;

#pragma unroll
                for (int ks = 0; ks < 4; ks++) {
                    uint32_t B[4];
                    ldsm4(B, rowb + (((ks * 2 + cselB) ^ lr) << 4));
#pragma unroll
                    for (int mt = 0; mt < 2; mt++) {
                        mma_f16(acc[mt][0], A[mt][ks], B[0], B[1]);
                        mma_f16(acc[mt][1], A[mt][ks], B[2], B[3]);
                    }
                }
                // c-fold MMA: adds c2hi[n]+c2lo[n] to every row
#pragma unroll
                for (int mt = 0; mt < 2; mt++) {
                    mma_f16(acc[mt][0], Aext, e0, 0u);
                    mma_f16(acc[mt][1], Aext, e1, 0u);
                }

                // epilogue: acc IS v; one prune region per mt
#pragma unroll
                for (int mt = 0; mt < 2; mt++) {
                    const int r0 = mt * 2, r1 = mt * 2 + 1;
                    float mx0 = fmaxf(fmaxf(acc[mt][0][0], acc[mt][0][1]),
                                      fmaxf(acc[mt][1][0], acc[mt][1][1]));
                    float mx1 = fmaxf(fmaxf(acc[mt][0][2], acc[mt][0][3]),
                                      fmaxf(acc[mt][1][2], acc[mt][1][3]));
                    if (fmaxf(mx0, mx1) > fminf(runm[r0], runm[r1]) - 20.f) {
                        float nm0 = fmaxf(runm[r0], mx0);
                        float nm1 = fmaxf(runm[r1], mx1);
                        runs[r0] = runs[r0] * ex2f(runm[r0] - nm0)
                                 + ((ex2f(acc[mt][0][0] - nm0) + ex2f(acc[mt][0][1] - nm0))
                                  + (ex2f(acc[mt][1][0] - nm0) + ex2f(acc[mt][1][1] - nm0)));
                        runs[r1] = runs[r1] * ex2f(runm[r1] - nm1)
                                 + ((ex2f(acc[mt][0][2] - nm1) + ex2f(acc[mt][0][3] - nm1))
                                  + (ex2f(acc[mt][1][2] - nm1) + ex2f(acc[mt][1][3] - nm1)));
                        runm[r0] = nm0;
                        runm[r1] = nm1;
                    }
                }
            }
        }

        // ---- merge across 4 q-lanes per row; write partials ----
#pragma unroll
        for (int r = 0; r < 4; r++) {
            float m = runm[r], s = runs[r];
#pragma unroll
            for (int off = 1; off < 4; off <<= 1) {
                float m2 = __shfl_xor_sync(0xffffffffu, m, off);
                float s2x = __shfl_xor_sync(0xffffffffu, s, off);
                float nm = fmaxf(m, m2);
                s = s * ex2f(m - nm) + s2x * ex2f(m2 - nm);
                m = nm;
            }
            if (q == 0) {
                int mt = r >> 1, hf = r & 1;
                int rl = mwarp * 32 + mt * 16 + hf * 8 + g4;
                int idx = ((rb * NCHUNK + ck) * 2 + nwarp) * BM + rl;
                g_pm[idx] = m;
                g_ps[idx] = s;
            }
        }

        // ---- steal next job ----
        if (tid == 0) job_s = atomicAdd(&g_job, 1);
        __syncthreads();
        job = job_s;
    }
}

// ---------------- finalize: merge 16 partials/row ----------------
__global__ void final_kernel(const float* __restrict__ X, float* __restrict__ out) {
    int r = blockIdx.x * blockDim.x + threadIdx.x;
    if (r >= N_SRC) return;
    int rb = r >> 7, rl = r & 127;
    const float invmv = g_scalars[0];
    const float mpsi  = g_scalars[2];
    float m = -INFINITY, s = 0.f;
#pragma unroll
    for (int ck = 0; ck < NCHUNK; ck++)
#pragma unroll
        for (int nw = 0; nw < 2; nw++) {
            int idx = ((rb * NCHUNK + ck) * 2 + nw) * BM + rl;
            float m2 = g_pm[idx], s2v = g_ps[idx];
            float nm = fmaxf(m, m2);
            s = s * ex2f(m - nm) + s2v * ex2f(m2 - nm);
            m = nm;
        }
    const float4* xr = reinterpret_cast<const float4*>(X + (size_t)r * D_DIM);
    float xs = 0.f;
#pragma unroll
    for (int i = 0; i < 16; i++) {
        float4 v = xr[i];
        xs = fmaf(v.x, v.x, fmaf(v.y, v.y, fmaf(v.z, v.z, fmaf(v.w, v.w, xs))));
    }
    out[r] = fmaf(xs, invmv, mpsi) - (REG_P * LN2) * (m + lg2f(s));
}

// ---------------- launch ----------------
extern "C" void kernel_launch(void* const* d_in, const int* in_sizes, int n_in,
                              void* d_out, int out_size) {
    const float *X = nullptr, *Y = nullptr, *psi = nullptr;
    for (int i = 0; i < n_in; i++) {
        if (in_sizes[i] == N_SRC * D_DIM)      X   = (const float*)d_in[i];
        else if (in_sizes[i] == M_TGT * D_DIM) Y   = (const float*)d_in[i];
        else if (in_sizes[i] == M_TGT)         psi = (const float*)d_in[i];
    }
    float* out = (float*)d_out;

    convY_tysq_kernel<<<(M_TGT * 8) / 256, 256>>>(Y);
    prep_kernel<<<1, 1024>>>(psi);
    convX_kernel<<<(N_SRC * D_DIM / 2 + 255) / 256, 256>>>(X);

    cudaFuncSetAttribute(lse_mma_kernel,
                         cudaFuncAttributeMaxDynamicSharedMemorySize, SM_TOTAL);
    lse_mma_kernel<<<GRID, NT, SM_TOTAL>>>();

    final_kernel<<<N_SRC / 256, 256>>>(X, out);
}

// round 13
// speedup vs baseline: 1.0446x; 1.0446x over previous
#include <cuda_runtime.h>
#include <cuda_fp16.h>
#include <math.h>
#include <cstdint>

#define N_SRC 32768
#define M_TGT 8192
#define D_DIM 64
#define REG_P 0.01f
#define INV_REG 100.0f
#define LOG2E 1.4426950408889634f
#define LN2 0.6931471805599453f

#define BM 128
#define BN 64
#define NT 256
#define NCPSM 3
#define GRID (148 * NCPSM)      // 444
#define NRB (N_SRC / BM)        // 256 row-blocks
#define NCHUNK 8
#define TPC 16                  // 64-row tiles per chunk
#define NJOBS (NRB * NCHUNK)    // 2048
#define NSTAGE 4

// ---------------- scratch ----------------
__device__ float  g_tysq[M_TGT];
__device__ float  g_c2[M_TGT];
__device__ float  g_scalars[4];      // 0: 1/mv, 1: 2*invmv*INV_REG*LOG2E, 2: mean(psi)
__device__ __half g_Xh[N_SRC * D_DIM];
__device__ __half g_Yh[M_TGT * D_DIM];
__device__ float  g_pm[NRB * NCHUNK * 2 * BM];
__device__ float  g_ps[NRB * NCHUNK * 2 * BM];
__device__ int    g_job;

// ---------------- helpers ----------------
__device__ __forceinline__ uint32_t smem_u32(const void* p) {
    uint32_t a;
    asm("{ .reg .u64 t; cvta.to.shared.u64 t, %1; cvt.u32.u64 %0, t; }" : "=r"(a) : "l"(p));
    return a;
}
__device__ __forceinline__ uint64_t gmem_u64(const void* p) {
    uint64_t a;
    asm("cvta.to.global.u64 %0, %1;" : "=l"(a) : "l"(p));
    return a;
}
__device__ __forceinline__ float ex2f(float x) {
    float r; asm("ex2.approx.ftz.f32 %0, %1;" : "=f"(r) : "f"(x)); return r;
}
__device__ __forceinline__ float lg2f(float x) {
    float r; asm("lg2.approx.f32 %0, %1;" : "=f"(r) : "f"(x)); return r;
}

#define CP_ASYNC16(s, g) \
    asm volatile("cp.async.cg.shared.global [%0], [%1], 16;" :: "r"(s), "l"(g))
#define CP_COMMIT() asm volatile("cp.async.commit_group;" ::: "memory")
#define CP_WAIT(n)  asm volatile("cp.async.wait_group %0;" :: "n"(n) : "memory")

__device__ __forceinline__ void ldsm4(uint32_t* r, uint32_t addr) {
    asm volatile("ldmatrix.sync.aligned.m8n8.x4.shared.b16 {%0,%1,%2,%3}, [%4];"
                 : "=r"(r[0]), "=r"(r[1]), "=r"(r[2]), "=r"(r[3]) : "r"(addr));
}
__device__ __forceinline__ void mma_f16(float* c, const uint32_t* a,
                                        uint32_t b0, uint32_t b1) {
    asm volatile("mma.sync.aligned.m16n8k16.row.col.f32.f16.f16.f32 "
                 "{%0,%1,%2,%3}, {%4,%5,%6,%7}, {%8,%9}, {%0,%1,%2,%3};"
                 : "+f"(c[0]), "+f"(c[1]), "+f"(c[2]), "+f"(c[3])
                 : "r"(a[0]), "r"(a[1]), "r"(a[2]), "r"(a[3]), "r"(b0), "r"(b1));
}

// smem layout (bytes): Xh 16KB | Yh 4x8KB | cs 4x256B
#define SM_X 0
#define SM_Y 16384
#define SM_C (16384 + NSTAGE * 8192)
#define SM_TOTAL (SM_C + NSTAGE * 256 + 128)

// ---------------- prologue kernels ----------------
__global__ void convX_kernel(const float* __restrict__ src) {
    int i = blockIdx.x * blockDim.x + threadIdx.x;
    if (i >= N_SRC * D_DIM / 2) return;
    float2 v = reinterpret_cast<const float2*>(src)[i];
    reinterpret_cast<__half2*>(g_Xh)[i] = __float22half2_rn(v);
}

__global__ void convY_tysq_kernel(const float* __restrict__ Y) {
    int gid = blockIdx.x * blockDim.x + threadIdx.x;
    int r = gid >> 3, c8 = gid & 7;
    const float4* p = reinterpret_cast<const float4*>(Y + (size_t)r * D_DIM + c8 * 8);
    float4 v0 = p[0], v1 = p[1];
    __half2 h[4];
    h[0] = __float22half2_rn(make_float2(v0.x, v0.y));
    h[1] = __float22half2_rn(make_float2(v0.z, v0.w));
    h[2] = __float22half2_rn(make_float2(v1.x, v1.y));
    h[3] = __float22half2_rn(make_float2(v1.z, v1.w));
    *reinterpret_cast<uint4*>(g_Yh + (size_t)r * D_DIM + c8 * 8) =
        *reinterpret_cast<uint4*>(h);
    float s = v0.x * v0.x + v0.y * v0.y + v0.z * v0.z + v0.w * v0.w
            + v1.x * v1.x + v1.y * v1.y + v1.z * v1.z + v1.w * v1.w;
    s += __shfl_down_sync(0xffffffffu, s, 4, 8);
    s += __shfl_down_sync(0xffffffffu, s, 2, 8);
    s += __shfl_down_sync(0xffffffffu, s, 1, 8);
    if (c8 == 0) g_tysq[r] = s;
}

__global__ void prep_kernel(const float* __restrict__ psi) {
    __shared__ float red_t[1024];
    __shared__ float red_p[1024];
    __shared__ float inv_mv_s;
    int t = threadIdx.x;
    float st = 0.f, sp = 0.f;
    for (int m = t; m < M_TGT; m += 1024) { st += g_tysq[m]; sp += psi[m]; }
    red_t[t] = st; red_p[t] = sp;
    __syncthreads();
    for (int off = 512; off > 0; off >>= 1) {
        if (t < off) { red_t[t] += red_t[t + off]; red_p[t] += red_p[t + off]; }
        __syncthreads();
    }
    if (t == 0) {
        float mv = red_t[0] / (float)M_TGT;
        float inv_mv = 1.0f / mv;
        g_scalars[0] = inv_mv;
        g_scalars[1] = 2.0f * inv_mv * INV_REG * LOG2E;
        g_scalars[2] = red_p[0] / (float)M_TGT;
        inv_mv_s = inv_mv;
        g_job = GRID;
    }
    __syncthreads();
    float inv_mv = inv_mv_s;
    for (int m = t; m < M_TGT; m += 1024)
        g_c2[m] = (psi[m] - g_tysq[m] * inv_mv) * (INV_REG * LOG2E);
}

// ---------------- main kernel ----------------
extern __shared__ char smem[];

__global__ __launch_bounds__(NT, NCPSM)
void lse_mma_kernel() {
    __shared__ int job_s;
    const uint32_t sb = smem_u32(smem);
    const int tid  = threadIdx.x;
    const int lane = tid & 31;
    const int wid  = tid >> 5;
    const int mwarp = wid >> 1;          // 0..3 -> rows mwarp*32..+31
    const int nwarp = wid & 1;           // 0..1 -> cols nwarp*32..+31
    const int q  = lane & 3;
    const int g4 = lane >> 2;

    const float s2 = g_scalars[1];

    const uint64_t Yg = gmem_u64(g_Yh);
    const uint64_t Cg = gmem_u64(g_c2);

    const int b = lane >> 3, lr = lane & 7;
    const int rselA = (b & 1) * 8, cselA = b >> 1;
    const int rselB = (b >> 1) * 8, cselB = b & 1;

    // kernel-invariant B-ldsm swizzle offsets per ks
    uint32_t boff[4];
#pragma unroll
    for (int ks = 0; ks < 4; ks++)
        boff[ks] = (uint32_t)(((ks * 2 + cselB) ^ lr) << 4);

    // hoisted per-thread prefetch offsets (Y tile = 512 x 16B chunks)
    uint32_t og[2], os[2];
#pragma unroll
    for (int i = 0; i < 2; i++) {
        int idx = tid + i * NT;
        int row = idx >> 3, ch = idx & 7;
        og[i] = (uint32_t)(row * 128 + ch * 16);
        os[i] = (uint32_t)(row * 128 + ((ch ^ (row & 7)) << 4));
    }

    int job = blockIdx.x;
    while (job < NJOBS) {
        const int rb = job >> 3;
        const int ck = job & 7;
        const int rowBase = rb * BM;
        const int tile0 = ck * TPC;

        // ---- X tile (fp16, 128 rows) -> smem ----
#pragma unroll
        for (int i = 0; i < 4; i++) {
            int idx = tid + i * NT;
            int row = idx >> 3, ch = idx & 7;
            uint4 v = *reinterpret_cast<const uint4*>(
                reinterpret_cast<const char*>(g_Xh) +
                (uint64_t)(rowBase + row) * 128 + ch * 16);
            *reinterpret_cast<uint4*>(smem + SM_X + row * 128 +
                                      ((ch ^ (row & 7)) << 4)) = v;
        }
        // ---- prefetch Y tiles 0..2 ----
#pragma unroll
        for (int pt = 0; pt < NSTAGE - 1; pt++) {
            uint64_t gb = Yg + (uint64_t)(tile0 + pt) * 8192;
            uint32_t sbase = sb + SM_Y + pt * 8192;
            CP_ASYNC16(sbase + os[0], gb + og[0]);
            CP_ASYNC16(sbase + os[1], gb + og[1]);
            if (tid < 16)
                CP_ASYNC16(sb + SM_C + pt * 256 + tid * 16,
                           Cg + (uint64_t)(tile0 + pt) * 256 + tid * 16);
            CP_COMMIT();
        }
        __syncthreads();

        // ---- A fragments (persistent for the job): 32 regs ----
        uint32_t A[2][4][4];
#pragma unroll
        for (int mt = 0; mt < 2; mt++)
#pragma unroll
            for (int ks = 0; ks < 4; ks++) {
                int row = mwarp * 32 + mt * 16 + rselA + lr;
                int ch  = ks * 2 + cselA;
                ldsm4(A[mt][ks], sb + SM_X + row * 128 + ((ch ^ lr) << 4));
            }

        float runm[4], runs[4];
#pragma unroll
        for (int r = 0; r < 4; r++) { runm[r] = -INFINITY; runs[r] = 0.f; }

        for (int t = 0; t < TPC; t++) {
            CP_WAIT(2);
            __syncthreads();
            const int buf = t & (NSTAGE - 1);
            const uint32_t yb = sb + SM_Y + buf * 8192;

            if (t + NSTAGE - 1 < TPC) {
                const int stg = (t + NSTAGE - 1) & (NSTAGE - 1);
                uint64_t gb = Yg + (uint64_t)(tile0 + t + NSTAGE - 1) * 8192;
                uint32_t sbase = sb + SM_Y + stg * 8192;
                CP_ASYNC16(sbase + os[0], gb + og[0]);
                CP_ASYNC16(sbase + os[1], gb + og[1]);
                if (tid < 16)
                    CP_ASYNC16(sb + SM_C + stg * 256 + tid * 16,
                               Cg + (uint64_t)(tile0 + t + NSTAGE - 1) * 256 + tid * 16);
            }
            CP_COMMIT();

#pragma unroll
            for (int nt2 = 0; nt2 < 2; nt2++) {
                const uint32_t rowb =
                    yb + (uint32_t)(nwarp * 32 + nt2 * 16 + rselB + lr) * 128;
                float2 cp0, cp1;
                {
                    const float* cbB =
                        reinterpret_cast<const float*>(smem + SM_C + buf * 256)
                        + nwarp * 32 + nt2 * 16;
                    cp0 = *reinterpret_cast<const float2*>(cbB + q * 2);
                    cp1 = *reinterpret_cast<const float2*>(cbB + 8 + q * 2);
                }
                float acc[2][2][4];
#pragma unroll
                for (int mt = 0; mt < 2; mt++)
#pragma unroll
                    for (int nf = 0; nf < 2; nf++)
#pragma unroll
                        for (int j = 0; j < 4; j++) acc[mt][nf][j] = 0.f;

                // software-pipelined B loads (depth 2) over ks
                uint32_t Bcur[4], Bnxt[4];
                ldsm4(Bcur, rowb + boff[0]);
#pragma unroll
                for (int ks = 0; ks < 4; ks++) {
                    if (ks < 3) ldsm4(Bnxt, rowb + boff[ks + 1]);
#pragma unroll
                    for (int mt = 0; mt < 2; mt++) {
                        mma_f16(acc[mt][0], A[mt][ks], Bcur[0], Bcur[1]);
                        mma_f16(acc[mt][1], A[mt][ks], Bcur[2], Bcur[3]);
                    }
#pragma unroll
                    for (int j = 0; j < 4; j++) Bcur[j] = Bnxt[j];
                }

                // epilogue: v = c + s2*dot; one prune region per mt
#pragma unroll
                for (int mt = 0; mt < 2; mt++) {
                    const int r0 = mt * 2, r1 = mt * 2 + 1;
                    float v00 = fmaf(s2, acc[mt][0][0], cp0.x);
                    float v01 = fmaf(s2, acc[mt][0][1], cp0.y);
                    float v02 = fmaf(s2, acc[mt][1][0], cp1.x);
                    float v03 = fmaf(s2, acc[mt][1][1], cp1.y);
                    float v10 = fmaf(s2, acc[mt][0][2], cp0.x);
                    float v11 = fmaf(s2, acc[mt][0][3], cp0.y);
                    float v12 = fmaf(s2, acc[mt][1][2], cp1.x);
                    float v13 = fmaf(s2, acc[mt][1][3], cp1.y);
                    float mx0 = fmaxf(fmaxf(v00, v01), fmaxf(v02, v03));
                    float mx1 = fmaxf(fmaxf(v10, v11), fmaxf(v12, v13));
                    if (fmaxf(mx0, mx1) > fminf(runm[r0], runm[r1]) - 15.f) {
                        float nm0 = fmaxf(runm[r0], mx0);
                        float nm1 = fmaxf(runm[r1], mx1);
                        runs[r0] = runs[r0] * ex2f(runm[r0] - nm0)
                                 + ((ex2f(v00 - nm0) + ex2f(v01 - nm0))
                                  + (ex2f(v02 - nm0) + ex2f(v03 - nm0)));
                        runs[r1] = runs[r1] * ex2f(runm[r1] - nm1)
                                 + ((ex2f(v10 - nm1) + ex2f(v11 - nm1))
                                  + (ex2f(v12 - nm1) + ex2f(v13 - nm1)));
                        runm[r0] = nm0;
                        runm[r1] = nm1;
                    }
                }
            }
        }

        // ---- merge across 4 q-lanes per row; write partials ----
#pragma unroll
        for (int r = 0; r < 4; r++) {
            float m = runm[r], s = runs[r];
#pragma unroll
            for (int off = 1; off < 4; off <<= 1) {
                float m2 = __shfl_xor_sync(0xffffffffu, m, off);
                float s2x = __shfl_xor_sync(0xffffffffu, s, off);
                float nm = fmaxf(m, m2);
                s = s * ex2f(m - nm) + s2x * ex2f(m2 - nm);
                m = nm;
            }
            if (q == 0) {
                int mt = r >> 1, hf = r & 1;
                int rl = mwarp * 32 + mt * 16 + hf * 8 + g4;
                int idx = ((rb * NCHUNK + ck) * 2 + nwarp) * BM + rl;
                g_pm[idx] = m;
                g_ps[idx] = s;
            }
        }

        // ---- steal next job ----
        if (tid == 0) job_s = atomicAdd(&g_job, 1);
        __syncthreads();
        job = job_s;
    }
}

// ---------------- finalize: merge 16 partials/row ----------------
__global__ void final_kernel(const float* __restrict__ X, float* __restrict__ out) {
    int r = blockIdx.x * blockDim.x + threadIdx.x;
    if (r >= N_SRC) return;
    int rb = r >> 7, rl = r & 127;
    const float invmv = g_scalars[0];
    const float mpsi  = g_scalars[2];
    float m = -INFINITY, s = 0.f;
#pragma unroll
    for (int ck = 0; ck < NCHUNK; ck++)
#pragma unroll
        for (int nw = 0; nw < 2; nw++) {
            int idx = ((rb * NCHUNK + ck) * 2 + nw) * BM + rl;
            float m2 = g_pm[idx], s2v = g_ps[idx];
            float nm = fmaxf(m, m2);
            s = s * ex2f(m - nm) + s2v * ex2f(m2 - nm);
            m = nm;
        }
    const float4* xr = reinterpret_cast<const float4*>(X + (size_t)r * D_DIM);
    float xs = 0.f;
#pragma unroll
    for (int i = 0; i < 16; i++) {
        float4 v = xr[i];
        xs = fmaf(v.x, v.x, fmaf(v.y, v.y, fmaf(v.z, v.z, fmaf(v.w, v.w, xs))));
    }
    out[r] = fmaf(xs, invmv, mpsi) - (REG_P * LN2) * (m + lg2f(s));
}

// ---------------- launch ----------------
extern "C" void kernel_launch(void* const* d_in, const int* in_sizes, int n_in,
                              void* d_out, int out_size) {
    const float *X = nullptr, *Y = nullptr, *psi = nullptr;
    for (int i = 0; i < n_in; i++) {
        if (in_sizes[i] == N_SRC * D_DIM)      X   = (const float*)d_in[i];
        else if (in_sizes[i] == M_TGT * D_DIM) Y   = (const float*)d_in[i];
        else if (in_sizes[i] == M_TGT)         psi = (const float*)d_in[i];
    }
    float* out = (float*)d_out;

    convX_kernel<<<(N_SRC * D_DIM / 2 + 255) / 256, 256>>>(X);
    convY_tysq_kernel<<<(M_TGT * 8) / 256, 256>>>(Y);
    prep_kernel<<<1, 1024>>>(psi);

    cudaFuncSetAttribute(lse_mma_kernel,
                         cudaFuncAttributeMaxDynamicSharedMemorySize, SM_TOTAL);
    lse_mma_kernel<<<GRID, NT, SM_TOTAL>>>();

    final_kernel<<<N_SRC / 256, 256>>>(X, out);
}

// round 14
// speedup vs baseline: 1.0555x; 1.0105x over previous
#include <cuda_runtime.h>
#include <cuda_fp16.h>
#include <math.h>
#include <cstdint>

#define N_SRC 32768
#define M_TGT 8192
#define D_DIM 64
#define REG_P 0.01f
#define INV_REG 100.0f
#define LOG2E 1.4426950408889634f
#define LN2 0.6931471805599453f

#define BM 128
#define BN 64
#define NT 256
#define NCPSM 3
#define GRID (148 * NCPSM)      // 444
#define NRB (N_SRC / BM)        // 256 row-blocks
#define NCHUNK 8
#define TPC 16                  // 64-row tiles per chunk
#define NJOBS (NRB * NCHUNK)    // 2048
#define NSTAGE 4

// ---------------- scratch ----------------
__device__ float  g_tysq[M_TGT];
__device__ float  g_c2[M_TGT];
__device__ float  g_scalars[4];      // 0: 1/mv, 1: 2*invmv*INV_REG*LOG2E, 2: mean(psi)
__device__ __half g_Xh[N_SRC * D_DIM];
__device__ __half g_Yh[M_TGT * D_DIM];
__device__ float  g_pm[NRB * NCHUNK * 2 * BM];
__device__ float  g_ps[NRB * NCHUNK * 2 * BM];
__device__ int    g_job;

// ---------------- helpers ----------------
__device__ __forceinline__ uint32_t smem_u32(const void* p) {
    uint32_t a;
    asm("{ .reg .u64 t; cvta.to.shared.u64 t, %1; cvt.u32.u64 %0, t; }" : "=r"(a) : "l"(p));
    return a;
}
__device__ __forceinline__ uint64_t gmem_u64(const void* p) {
    uint64_t a;
    asm("cvta.to.global.u64 %0, %1;" : "=l"(a) : "l"(p));
    return a;
}
__device__ __forceinline__ float ex2f(float x) {
    float r; asm("ex2.approx.ftz.f32 %0, %1;" : "=f"(r) : "f"(x)); return r;
}
__device__ __forceinline__ float lg2f(float x) {
    float r; asm("lg2.approx.f32 %0, %1;" : "=f"(r) : "f"(x)); return r;
}

#define CP_ASYNC16(s, g) \
    asm volatile("cp.async.cg.shared.global [%0], [%1], 16;" :: "r"(s), "l"(g))
#define CP_COMMIT() asm volatile("cp.async.commit_group;" ::: "memory")
#define CP_WAIT(n)  asm volatile("cp.async.wait_group %0;" :: "n"(n) : "memory")

__device__ __forceinline__ void ldsm4(uint32_t* r, uint32_t addr) {
    asm volatile("ldmatrix.sync.aligned.m8n8.x4.shared.b16 {%0,%1,%2,%3}, [%4];"
                 : "=r"(r[0]), "=r"(r[1]), "=r"(r[2]), "=r"(r[3]) : "r"(addr));
}
// accumulate in place: d == c
__device__ __forceinline__ void mma_f16(float* c, const uint32_t* a,
                                        uint32_t b0, uint32_t b1) {
    asm volatile("mma.sync.aligned.m16n8k16.row.col.f32.f16.f16.f32 "
                 "{%0,%1,%2,%3}, {%4,%5,%6,%7}, {%8,%9}, {%0,%1,%2,%3};"
                 : "+f"(c[0]), "+f"(c[1]), "+f"(c[2]), "+f"(c[3])
                 : "r"(a[0]), "r"(a[1]), "r"(a[2]), "r"(a[3]), "r"(b0), "r"(b1));
}
// separate d and c: d = a*b + c  (kills acc-zeroing MOVs on first k-step)
__device__ __forceinline__ void mma_f16_dc(float* d, const uint32_t* a,
                                           uint32_t b0, uint32_t b1,
                                           const float* c) {
    asm volatile("mma.sync.aligned.m16n8k16.row.col.f32.f16.f16.f32 "
                 "{%0,%1,%2,%3}, {%4,%5,%6,%7}, {%8,%9}, {%10,%11,%12,%13};"
                 : "=f"(d[0]), "=f"(d[1]), "=f"(d[2]), "=f"(d[3])
                 : "r"(a[0]), "r"(a[1]), "r"(a[2]), "r"(a[3]), "r"(b0), "r"(b1),
                   "f"(c[0]), "f"(c[1]), "f"(c[2]), "f"(c[3]));
}

// smem layout (bytes): Xh 16KB | Yh 4x8KB | cs 4x256B
#define SM_X 0
#define SM_Y 16384
#define SM_C (16384 + NSTAGE * 8192)
#define SM_TOTAL (SM_C + NSTAGE * 256 + 128)

// ---------------- prologue kernels ----------------
__global__ void convX_kernel(const float* __restrict__ src) {
    int i = blockIdx.x * blockDim.x + threadIdx.x;
    if (i >= N_SRC * D_DIM / 2) return;
    float2 v = reinterpret_cast<const float2*>(src)[i];
    reinterpret_cast<__half2*>(g_Xh)[i] = __float22half2_rn(v);
}

__global__ void convY_tysq_kernel(const float* __restrict__ Y) {
    int gid = blockIdx.x * blockDim.x + threadIdx.x;
    int r = gid >> 3, c8 = gid & 7;
    const float4* p = reinterpret_cast<const float4*>(Y + (size_t)r * D_DIM + c8 * 8);
    float4 v0 = p[0], v1 = p[1];
    __half2 h[4];
    h[0] = __float22half2_rn(make_float2(v0.x, v0.y));
    h[1] = __float22half2_rn(make_float2(v0.z, v0.w));
    h[2] = __float22half2_rn(make_float2(v1.x, v1.y));
    h[3] = __float22half2_rn(make_float2(v1.z, v1.w));
    *reinterpret_cast<uint4*>(g_Yh + (size_t)r * D_DIM + c8 * 8) =
        *reinterpret_cast<uint4*>(h);
    float s = v0.x * v0.x + v0.y * v0.y + v0.z * v0.z + v0.w * v0.w
            + v1.x * v1.x + v1.y * v1.y + v1.z * v1.z + v1.w * v1.w;
    s += __shfl_down_sync(0xffffffffu, s, 4, 8);
    s += __shfl_down_sync(0xffffffffu, s, 2, 8);
    s += __shfl_down_sync(0xffffffffu, s, 1, 8);
    if (c8 == 0) g_tysq[r] = s;
}

__global__ void prep_kernel(const float* __restrict__ psi) {
    __shared__ float red_t[1024];
    __shared__ float red_p[1024];
    __shared__ float inv_mv_s;
    int t = threadIdx.x;
    float st = 0.f, sp = 0.f;
    for (int m = t; m < M_TGT; m += 1024) { st += g_tysq[m]; sp += psi[m]; }
    red_t[t] = st; red_p[t] = sp;
    __syncthreads();
    for (int off = 512; off > 0; off >>= 1) {
        if (t < off) { red_t[t] += red_t[t + off]; red_p[t] += red_p[t + off]; }
        __syncthreads();
    }
    if (t == 0) {
        float mv = red_t[0] / (float)M_TGT;
        float inv_mv = 1.0f / mv;
        g_scalars[0] = inv_mv;
        g_scalars[1] = 2.0f * inv_mv * INV_REG * LOG2E;
        g_scalars[2] = red_p[0] / (float)M_TGT;
        inv_mv_s = inv_mv;
        g_job = GRID;
    }
    __syncthreads();
    float inv_mv = inv_mv_s;
    for (int m = t; m < M_TGT; m += 1024)
        g_c2[m] = (psi[m] - g_tysq[m] * inv_mv) * (INV_REG * LOG2E);
}

// ---------------- main kernel ----------------
extern __shared__ char smem[];

__global__ __launch_bounds__(NT, NCPSM)
void lse_mma_kernel() {
    __shared__ int job_s;
    const uint32_t sb = smem_u32(smem);
    const int tid  = threadIdx.x;
    const int lane = tid & 31;
    const int wid  = tid >> 5;
    const int mwarp = wid >> 1;          // 0..3 -> rows mwarp*32..+31
    const int nwarp = wid & 1;           // 0..1 -> cols nwarp*32..+31
    const int q  = lane & 3;
    const int g4 = lane >> 2;

    const float s2 = g_scalars[1];

    const uint64_t Yg = gmem_u64(g_Yh);
    const uint64_t Cg = gmem_u64(g_c2);

    const int b = lane >> 3, lr = lane & 7;
    const int rselA = (b & 1) * 8, cselA = b >> 1;
    const int rselB = (b >> 1) * 8, cselB = b & 1;

    // zero quad for first-k-step MMA C operand
    float zc[4];
#pragma unroll
    for (int j = 0; j < 4; j++) zc[j] = 0.f;

    // kernel-invariant B-ldsm swizzle offsets per ks
    uint32_t boff[4];
#pragma unroll
    for (int ks = 0; ks < 4; ks++)
        boff[ks] = (uint32_t)(((ks * 2 + cselB) ^ lr) << 4);

    // hoisted per-thread prefetch offsets
    uint32_t og[2], os[2];
#pragma unroll
    for (int i = 0; i < 2; i++) {
        int idx = tid + i * NT;
        int row = idx >> 3, ch = idx & 7;
        og[i] = (uint32_t)(row * 128 + ch * 16);
        os[i] = (uint32_t)(row * 128 + ((ch ^ (row & 7)) << 4));
    }

    int job = blockIdx.x;
    while (job < NJOBS) {
        const int rb = job >> 3;
        const int ck = job & 7;
        const int rowBase = rb * BM;
        const int tile0 = ck * TPC;

        // ---- X tile (fp16, 128 rows) -> smem ----
#pragma unroll
        for (int i = 0; i < 4; i++) {
            int idx = tid + i * NT;
            int row = idx >> 3, ch = idx & 7;
            uint4 v = *reinterpret_cast<const uint4*>(
                reinterpret_cast<const char*>(g_Xh) +
                (uint64_t)(rowBase + row) * 128 + ch * 16);
            *reinterpret_cast<uint4*>(smem + SM_X + row * 128 +
                                      ((ch ^ (row & 7)) << 4)) = v;
        }
        // ---- prefetch Y tiles 0..2 ----
#pragma unroll
        for (int pt = 0; pt < NSTAGE - 1; pt++) {
            uint64_t gb = Yg + (uint64_t)(tile0 + pt) * 8192;
            uint32_t sbase = sb + SM_Y + pt * 8192;
            CP_ASYNC16(sbase + os[0], gb + og[0]);
            CP_ASYNC16(sbase + os[1], gb + og[1]);
            if (tid < 16)
                CP_ASYNC16(sb + SM_C + pt * 256 + tid * 16,
                           Cg + (uint64_t)(tile0 + pt) * 256 + tid * 16);
            CP_COMMIT();
        }
        __syncthreads();

        // ---- A fragments (persistent for the job): 32 regs ----
        uint32_t A[2][4][4];
#pragma unroll
        for (int mt = 0; mt < 2; mt++)
#pragma unroll
            for (int ks = 0; ks < 4; ks++) {
                int row = mwarp * 32 + mt * 16 + rselA + lr;
                int ch  = ks * 2 + cselA;
                ldsm4(A[mt][ks], sb + SM_X + row * 128 + ((ch ^ lr) << 4));
            }

        float runm[4], runs[4];
#pragma unroll
        for (int r = 0; r < 4; r++) { runm[r] = -INFINITY; runs[r] = 0.f; }

        for (int t = 0; t < TPC; t++) {
            CP_WAIT(2);
            __syncthreads();
            const int buf = t & (NSTAGE - 1);
            const uint32_t yb = sb + SM_Y + buf * 8192;

            if (t + NSTAGE - 1 < TPC) {
                const int stg = (t + NSTAGE - 1) & (NSTAGE - 1);
                uint64_t gb = Yg + (uint64_t)(tile0 + t + NSTAGE - 1) * 8192;
                uint32_t sbase = sb + SM_Y + stg * 8192;
                CP_ASYNC16(sbase + os[0], gb + og[0]);
                CP_ASYNC16(sbase + os[1], gb + og[1]);
                if (tid < 16)
                    CP_ASYNC16(sb + SM_C + stg * 256 + tid * 16,
                               Cg + (uint64_t)(tile0 + t + NSTAGE - 1) * 256 + tid * 16);
            }
            CP_COMMIT();

#pragma unroll
            for (int nt2 = 0; nt2 < 2; nt2++) {
                const uint32_t rowb =
                    yb + (uint32_t)(nwarp * 32 + nt2 * 16 + rselB + lr) * 128;
                float2 cp0, cp1;
                {
                    const float* cbB =
                        reinterpret_cast<const float*>(smem + SM_C + buf * 256)
                        + nwarp * 32 + nt2 * 16;
                    cp0 = *reinterpret_cast<const float2*>(cbB + q * 2);
                    cp1 = *reinterpret_cast<const float2*>(cbB + 8 + q * 2);
                }

                float acc[2][2][4];
                uint32_t Ba[4], Bb[4];
                // depth-2 ping-pong ldsm pipeline, fully unrolled (no copies)
                ldsm4(Ba, rowb + boff[0]);
                ldsm4(Bb, rowb + boff[1]);
                // ks = 0 : first step uses separate-C MMA (acc = a*b + 0)
#pragma unroll
                for (int mt = 0; mt < 2; mt++) {
                    mma_f16_dc(acc[mt][0], A[mt][0], Ba[0], Ba[1], zc);
                    mma_f16_dc(acc[mt][1], A[mt][0], Ba[2], Ba[3], zc);
                }
                ldsm4(Ba, rowb + boff[2]);
                // ks = 1
#pragma unroll
                for (int mt = 0; mt < 2; mt++) {
                    mma_f16(acc[mt][0], A[mt][1], Bb[0], Bb[1]);
                    mma_f16(acc[mt][1], A[mt][1], Bb[2], Bb[3]);
                }
                ldsm4(Bb, rowb + boff[3]);
                // ks = 2
#pragma unroll
                for (int mt = 0; mt < 2; mt++) {
                    mma_f16(acc[mt][0], A[mt][2], Ba[0], Ba[1]);
                    mma_f16(acc[mt][1], A[mt][2], Ba[2], Ba[3]);
                }
                // ks = 3
#pragma unroll
                for (int mt = 0; mt < 2; mt++) {
                    mma_f16(acc[mt][0], A[mt][3], Bb[0], Bb[1]);
                    mma_f16(acc[mt][1], A[mt][3], Bb[2], Bb[3]);
                }

                // epilogue: v = c + s2*dot; one prune region per mt
#pragma unroll
                for (int mt = 0; mt < 2; mt++) {
                    const int r0 = mt * 2, r1 = mt * 2 + 1;
                    float v00 = fmaf(s2, acc[mt][0][0], cp0.x);
                    float v01 = fmaf(s2, acc[mt][0][1], cp0.y);
                    float v02 = fmaf(s2, acc[mt][1][0], cp1.x);
                    float v03 = fmaf(s2, acc[mt][1][1], cp1.y);
                    float v10 = fmaf(s2, acc[mt][0][2], cp0.x);
                    float v11 = fmaf(s2, acc[mt][0][3], cp0.y);
                    float v12 = fmaf(s2, acc[mt][1][2], cp1.x);
                    float v13 = fmaf(s2, acc[mt][1][3], cp1.y);
                    float mx0 = fmaxf(fmaxf(v00, v01), fmaxf(v02, v03));
                    float mx1 = fmaxf(fmaxf(v10, v11), fmaxf(v12, v13));
                    if (fmaxf(mx0, mx1) > fminf(runm[r0], runm[r1]) - 15.f) {
                        float nm0 = fmaxf(runm[r0], mx0);
                        float nm1 = fmaxf(runm[r1], mx1);
                        runs[r0] = runs[r0] * ex2f(runm[r0] - nm0)
                                 + ((ex2f(v00 - nm0) + ex2f(v01 - nm0))
                                  + (ex2f(v02 - nm0) + ex2f(v03 - nm0)));
                        runs[r1] = runs[r1] * ex2f(runm[r1] - nm1)
                                 + ((ex2f(v10 - nm1) + ex2f(v11 - nm1))
                                  + (ex2f(v12 - nm1) + ex2f(v13 - nm1)));
                        runm[r0] = nm0;
                        runm[r1] = nm1;
                    }
                }
            }
        }

        // ---- merge across 4 q-lanes per row; write partials ----
#pragma unroll
        for (int r = 0; r < 4; r++) {
            float m = runm[r], s = runs[r];
#pragma unroll
            for (int off = 1; off < 4; off <<= 1) {
                float m2 = __shfl_xor_sync(0xffffffffu, m, off);
                float s2x = __shfl_xor_sync(0xffffffffu, s, off);
                float nm = fmaxf(m, m2);
                s = s * ex2f(m - nm) + s2x * ex2f(m2 - nm);
                m = nm;
            }
            if (q == 0) {
                int mt = r >> 1, hf = r & 1;
                int rl = mwarp * 32 + mt * 16 + hf * 8 + g4;
                int idx = ((rb * NCHUNK + ck) * 2 + nwarp) * BM + rl;
                g_pm[idx] = m;
                g_ps[idx] = s;
            }
        }

        // ---- steal next job ----
        if (tid == 0) job_s = atomicAdd(&g_job, 1);
        __syncthreads();
        job = job_s;
    }
}

// ---------------- finalize: merge 16 partials/row ----------------
__global__ void final_kernel(const float* __restrict__ X, float* __restrict__ out) {
    int r = blockIdx.x * blockDim.x + threadIdx.x;
    if (r >= N_SRC) return;
    int rb = r >> 7, rl = r & 127;
    const float invmv = g_scalars[0];
    const float mpsi  = g_scalars[2];
    float m = -INFINITY, s = 0.f;
#pragma unroll
    for (int ck = 0; ck < NCHUNK; ck++)
#pragma unroll
        for (int nw = 0; nw < 2; nw++) {
            int idx = ((rb * NCHUNK + ck) * 2 + nw) * BM + rl;
            float m2 = g_pm[idx], s2v = g_ps[idx];
            float nm = fmaxf(m, m2);
            s = s * ex2f(m - nm) + s2v * ex2f(m2 - nm);
            m = nm;
        }
    const float4* xr = reinterpret_cast<const float4*>(X + (size_t)r * D_DIM);
    float xs = 0.f;
#pragma unroll
    for (int i = 0; i < 16; i++) {
        float4 v = xr[i];
        xs = fmaf(v.x, v.x, fmaf(v.y, v.y, fmaf(v.z, v.z, fmaf(v.w, v.w, xs))));
    }
    out[r] = fmaf(xs, invmv, mpsi) - (REG_P * LN2) * (m + lg2f(s));
}

// ---------------- launch ----------------
extern "C" void kernel_launch(void* const* d_in, const int* in_sizes, int n_in,
                              void* d_out, int out_size) {
    const float *X = nullptr, *Y = nullptr, *psi = nullptr;
    for (int i = 0; i < n_in; i++) {
        if (in_sizes[i] == N_SRC * D_DIM)      X   = (const float*)d_in[i];
        else if (in_sizes[i] == M_TGT * D_DIM) Y   = (const float*)d_in[i];
        else if (in_sizes[i] == M_TGT)         psi = (const float*)d_in[i];
    }
    float* out = (float*)d_out;

    convX_kernel<<<(N_SRC * D_DIM / 2 + 255) / 256, 256>>>(X);
    convY_tysq_kernel<<<(M_TGT * 8) / 256, 256>>>(Y);
    prep_kernel<<<1, 1024>>>(psi);

    cudaFuncSetAttribute(lse_mma_kernel,
                         cudaFuncAttributeMaxDynamicSharedMemorySize, SM_TOTAL);
    lse_mma_kernel<<<GRID, NT, SM_TOTAL>>>();

    final_kernel<<<N_SRC / 256, 256>>>(X, out);
}

// round 15
// speedup vs baseline: 1.1759x; 1.1140x over previous
#include <cuda_runtime.h>
#include <cuda_fp16.h>
#include <math.h>
#include <cstdint>

#define N_SRC 32768
#define M_TGT 8192
#define D_DIM 64
#define REG_P 0.01f
#define INV_REG 100.0f
#define LOG2E 1.4426950408889634f
#define LN2 0.6931471805599453f

#define BM 128
#define BN 64
#define NT 256
#define NCPSM 4
#define GRID (148 * NCPSM)      // 592
#define NRB (N_SRC / BM)        // 256 row-blocks
#define NCHUNK 8
#define TPC 16                  // 64-row tiles per chunk
#define NJOBS (NRB * NCHUNK)    // 2048
#define NSTAGE 4

// ---------------- scratch ----------------
__device__ float  g_tysq[M_TGT];
__device__ float  g_c2[M_TGT];
__device__ float  g_scalars[4];      // 0: 1/mv, 1: 2*invmv*INV_REG*LOG2E, 2: mean(psi)
__device__ __half g_Xh[N_SRC * D_DIM];
__device__ __half g_Yh[M_TGT * D_DIM];
__device__ float  g_pm[NRB * NCHUNK * BM];   // [rb][ck][row]
__device__ float  g_ps[NRB * NCHUNK * BM];
__device__ int    g_job;

// ---------------- helpers ----------------
__device__ __forceinline__ uint32_t smem_u32(const void* p) {
    uint32_t a;
    asm("{ .reg .u64 t; cvta.to.shared.u64 t, %1; cvt.u32.u64 %0, t; }" : "=r"(a) : "l"(p));
    return a;
}
__device__ __forceinline__ uint64_t gmem_u64(const void* p) {
    uint64_t a;
    asm("cvta.to.global.u64 %0, %1;" : "=l"(a) : "l"(p));
    return a;
}
__device__ __forceinline__ float ex2f(float x) {
    float r; asm("ex2.approx.ftz.f32 %0, %1;" : "=f"(r) : "f"(x)); return r;
}
__device__ __forceinline__ float lg2f(float x) {
    float r; asm("lg2.approx.f32 %0, %1;" : "=f"(r) : "f"(x)); return r;
}

#define CP_ASYNC16(s, g) \
    asm volatile("cp.async.cg.shared.global [%0], [%1], 16;" :: "r"(s), "l"(g))
#define CP_COMMIT() asm volatile("cp.async.commit_group;" ::: "memory")
#define CP_WAIT(n)  asm volatile("cp.async.wait_group %0;" :: "n"(n) : "memory")

__device__ __forceinline__ void ldsm4(uint32_t* r, uint32_t addr) {
    asm volatile("ldmatrix.sync.aligned.m8n8.x4.shared.b16 {%0,%1,%2,%3}, [%4];"
                 : "=r"(r[0]), "=r"(r[1]), "=r"(r[2]), "=r"(r[3]) : "r"(addr));
}
__device__ __forceinline__ void mma_f16(float* c, const uint32_t* a,
                                        uint32_t b0, uint32_t b1) {
    asm volatile("mma.sync.aligned.m16n8k16.row.col.f32.f16.f16.f32 "
                 "{%0,%1,%2,%3}, {%4,%5,%6,%7}, {%8,%9}, {%0,%1,%2,%3};"
                 : "+f"(c[0]), "+f"(c[1]), "+f"(c[2]), "+f"(c[3])
                 : "r"(a[0]), "r"(a[1]), "r"(a[2]), "r"(a[3]), "r"(b0), "r"(b1));
}
__device__ __forceinline__ void mma_f16_dc(float* d, const uint32_t* a,
                                           uint32_t b0, uint32_t b1,
                                           const float* c) {
    asm volatile("mma.sync.aligned.m16n8k16.row.col.f32.f16.f16.f32 "
                 "{%0,%1,%2,%3}, {%4,%5,%6,%7}, {%8,%9}, {%10,%11,%12,%13};"
                 : "=f"(d[0]), "=f"(d[1]), "=f"(d[2]), "=f"(d[3])
                 : "r"(a[0]), "r"(a[1]), "r"(a[2]), "r"(a[3]), "r"(b0), "r"(b1),
                   "f"(c[0]), "f"(c[1]), "f"(c[2]), "f"(c[3]));
}

// smem layout (bytes): Xh 16KB | Yh 4x8KB | cs 4x256B
#define SM_X 0
#define SM_Y 16384
#define SM_C (16384 + NSTAGE * 8192)
#define SM_TOTAL (SM_C + NSTAGE * 256 + 128)   // ~50.3 KB; x4 CTAs fits

// ---------------- prologue kernels ----------------
__global__ void convX_kernel(const float* __restrict__ src) {
    int i = blockIdx.x * blockDim.x + threadIdx.x;
    if (i >= N_SRC * D_DIM / 2) return;
    float2 v = reinterpret_cast<const float2*>(src)[i];
    reinterpret_cast<__half2*>(g_Xh)[i] = __float22half2_rn(v);
}

__global__ void convY_tysq_kernel(const float* __restrict__ Y) {
    int gid = blockIdx.x * blockDim.x + threadIdx.x;
    int r = gid >> 3, c8 = gid & 7;
    const float4* p = reinterpret_cast<const float4*>(Y + (size_t)r * D_DIM + c8 * 8);
    float4 v0 = p[0], v1 = p[1];
    __half2 h[4];
    h[0] = __float22half2_rn(make_float2(v0.x, v0.y));
    h[1] = __float22half2_rn(make_float2(v0.z, v0.w));
    h[2] = __float22half2_rn(make_float2(v1.x, v1.y));
    h[3] = __float22half2_rn(make_float2(v1.z, v1.w));
    *reinterpret_cast<uint4*>(g_Yh + (size_t)r * D_DIM + c8 * 8) =
        *reinterpret_cast<uint4*>(h);
    float s = v0.x * v0.x + v0.y * v0.y + v0.z * v0.z + v0.w * v0.w
            + v1.x * v1.x + v1.y * v1.y + v1.z * v1.z + v1.w * v1.w;
    s += __shfl_down_sync(0xffffffffu, s, 4, 8);
    s += __shfl_down_sync(0xffffffffu, s, 2, 8);
    s += __shfl_down_sync(0xffffffffu, s, 1, 8);
    if (c8 == 0) g_tysq[r] = s;
}

__global__ void prep_kernel(const float* __restrict__ psi) {
    __shared__ float red_t[1024];
    __shared__ float red_p[1024];
    __shared__ float inv_mv_s;
    int t = threadIdx.x;
    float st = 0.f, sp = 0.f;
    for (int m = t; m < M_TGT; m += 1024) { st += g_tysq[m]; sp += psi[m]; }
    red_t[t] = st; red_p[t] = sp;
    __syncthreads();
    for (int off = 512; off > 0; off >>= 1) {
        if (t < off) { red_t[t] += red_t[t + off]; red_p[t] += red_p[t + off]; }
        __syncthreads();
    }
    if (t == 0) {
        float mv = red_t[0] / (float)M_TGT;
        float inv_mv = 1.0f / mv;
        g_scalars[0] = inv_mv;
        g_scalars[1] = 2.0f * inv_mv * INV_REG * LOG2E;
        g_scalars[2] = red_p[0] / (float)M_TGT;
        inv_mv_s = inv_mv;
        g_job = GRID;
    }
    __syncthreads();
    float inv_mv = inv_mv_s;
    for (int m = t; m < M_TGT; m += 1024)
        g_c2[m] = (psi[m] - g_tysq[m] * inv_mv) * (INV_REG * LOG2E);
}

// ---------------- main kernel: 8 warps x 16-row tiles, 4 CTAs/SM ----------
extern __shared__ char smem[];

__global__ __launch_bounds__(NT, NCPSM)
void lse_mma_kernel() {
    __shared__ int job_s;
    const uint32_t sb = smem_u32(smem);
    const int tid  = threadIdx.x;
    const int lane = tid & 31;
    const int wid  = tid >> 5;           // row group: rows wid*16..+15
    const int q  = lane & 3;
    const int g4 = lane >> 2;

    const float s2 = g_scalars[1];

    const uint64_t Yg = gmem_u64(g_Yh);
    const uint64_t Cg = gmem_u64(g_c2);

    const int b = lane >> 3, lr = lane & 7;
    const int rselA = (b & 1) * 8, cselA = b >> 1;
    const int rselB = (b >> 1) * 8, cselB = b & 1;

    float zc[4];
#pragma unroll
    for (int j = 0; j < 4; j++) zc[j] = 0.f;

    uint32_t boff[4];
#pragma unroll
    for (int ks = 0; ks < 4; ks++)
        boff[ks] = (uint32_t)(((ks * 2 + cselB) ^ lr) << 4);

    int job = blockIdx.x;
    while (job < NJOBS) {
        const int rb = job >> 3;
        const int ck = job & 7;
        const int rowBase = rb * BM;
        const int tile0 = ck * TPC;

        // ---- X tile (fp16, 128 rows) -> smem ----
#pragma unroll
        for (int i = 0; i < 4; i++) {
            int idx = tid + i * NT;
            int row = idx >> 3, ch = idx & 7;
            uint4 v = *reinterpret_cast<const uint4*>(
                reinterpret_cast<const char*>(g_Xh) +
                (uint64_t)(rowBase + row) * 128 + ch * 16);
            *reinterpret_cast<uint4*>(smem + SM_X + row * 128 +
                                      ((ch ^ (row & 7)) << 4)) = v;
        }
        // ---- prefetch Y tiles 0..2 ----
#pragma unroll
        for (int pt = 0; pt < NSTAGE - 1; pt++) {
            uint64_t gb = Yg + (uint64_t)(tile0 + pt) * 8192;
            uint32_t sbase = sb + SM_Y + pt * 8192;
#pragma unroll
            for (int i = 0; i < 2; i++) {
                int idx = tid + i * NT;
                int row = idx >> 3, ch = idx & 7;
                CP_ASYNC16(sbase + row * 128 + ((ch ^ (row & 7)) << 4),
                           gb + row * 128 + ch * 16);
            }
            if (tid < 16)
                CP_ASYNC16(sb + SM_C + pt * 256 + tid * 16,
                           Cg + (uint64_t)(tile0 + pt) * 256 + tid * 16);
            CP_COMMIT();
        }
        __syncthreads();

        // ---- A fragments (persistent, 16 rows): 16 regs, 4 ldsm ----
        uint32_t A[4][4];
#pragma unroll
        for (int ks = 0; ks < 4; ks++) {
            int row = wid * 16 + rselA + lr;
            int ch  = ks * 2 + cselA;
            ldsm4(A[ks], sb + SM_X + row * 128 + ((ch ^ lr) << 4));
        }

        float runm[2], runs[2];      // row g4, row g4+8
        runm[0] = runm[1] = -INFINITY;
        runs[0] = runs[1] = 0.f;

        for (int t = 0; t < TPC; t++) {
            CP_WAIT(2);
            __syncthreads();
            const int buf = t & (NSTAGE - 1);
            const uint32_t yb = sb + SM_Y + buf * 8192;

            if (t + NSTAGE - 1 < TPC) {
                const int stg = (t + NSTAGE - 1) & (NSTAGE - 1);
                uint64_t gb = Yg + (uint64_t)(tile0 + t + NSTAGE - 1) * 8192;
                uint32_t sbase = sb + SM_Y + stg * 8192;
#pragma unroll
                for (int i = 0; i < 2; i++) {
                    int idx = tid + i * NT;
                    int row = idx >> 3, ch = idx & 7;
                    CP_ASYNC16(sbase + row * 128 + ((ch ^ (row & 7)) << 4),
                               gb + row * 128 + ch * 16);
                }
                if (tid < 16)
                    CP_ASYNC16(sb + SM_C + stg * 256 + tid * 16,
                               Cg + (uint64_t)(tile0 + t + NSTAGE - 1) * 256 + tid * 16);
            }
            CP_COMMIT();

#pragma unroll
            for (int nt4 = 0; nt4 < 4; nt4++) {       // 16-col groups
                const uint32_t rowb =
                    yb + (uint32_t)(nt4 * 16 + rselB + lr) * 128;
                float2 cp0, cp1;
                {
                    const float* cbB =
                        reinterpret_cast<const float*>(smem + SM_C + buf * 256)
                        + nt4 * 16;
                    cp0 = *reinterpret_cast<const float2*>(cbB + q * 2);
                    cp1 = *reinterpret_cast<const float2*>(cbB + 8 + q * 2);
                }

                float acc[2][4];
                uint32_t Ba[4], Bb[4];
                ldsm4(Ba, rowb + boff[0]);
                ldsm4(Bb, rowb + boff[1]);
                mma_f16_dc(acc[0], A[0], Ba[0], Ba[1], zc);
                mma_f16_dc(acc[1], A[0], Ba[2], Ba[3], zc);
                ldsm4(Ba, rowb + boff[2]);
                mma_f16(acc[0], A[1], Bb[0], Bb[1]);
                mma_f16(acc[1], A[1], Bb[2], Bb[3]);
                ldsm4(Bb, rowb + boff[3]);
                mma_f16(acc[0], A[2], Ba[0], Ba[1]);
                mma_f16(acc[1], A[2], Ba[2], Ba[3]);
                mma_f16(acc[0], A[3], Bb[0], Bb[1]);
                mma_f16(acc[1], A[3], Bb[2], Bb[3]);

                // epilogue: v = c + s2*dot; one prune region per nt4
                float v00 = fmaf(s2, acc[0][0], cp0.x);
                float v01 = fmaf(s2, acc[0][1], cp0.y);
                float v02 = fmaf(s2, acc[1][0], cp1.x);
                float v03 = fmaf(s2, acc[1][1], cp1.y);
                float v10 = fmaf(s2, acc[0][2], cp0.x);
                float v11 = fmaf(s2, acc[0][3], cp0.y);
                float v12 = fmaf(s2, acc[1][2], cp1.x);
                float v13 = fmaf(s2, acc[1][3], cp1.y);
                float mx0 = fmaxf(fmaxf(v00, v01), fmaxf(v02, v03));
                float mx1 = fmaxf(fmaxf(v10, v11), fmaxf(v12, v13));
                if (fmaxf(mx0, mx1) > fminf(runm[0], runm[1]) - 15.f) {
                    float nm0 = fmaxf(runm[0], mx0);
                    float nm1 = fmaxf(runm[1], mx1);
                    runs[0] = runs[0] * ex2f(runm[0] - nm0)
                            + ((ex2f(v00 - nm0) + ex2f(v01 - nm0))
                             + (ex2f(v02 - nm0) + ex2f(v03 - nm0)));
                    runs[1] = runs[1] * ex2f(runm[1] - nm1)
                            + ((ex2f(v10 - nm1) + ex2f(v11 - nm1))
                             + (ex2f(v12 - nm1) + ex2f(v13 - nm1)));
                    runm[0] = nm0;
                    runm[1] = nm1;
                }
            }
        }

        // ---- merge across 4 q-lanes per row; write partials ----
#pragma unroll
        for (int r = 0; r < 2; r++) {
            float m = runm[r], s = runs[r];
#pragma unroll
            for (int off = 1; off < 4; off <<= 1) {
                float m2 = __shfl_xor_sync(0xffffffffu, m, off);
                float s2x = __shfl_xor_sync(0xffffffffu, s, off);
                float nm = fmaxf(m, m2);
                s = s * ex2f(m - nm) + s2x * ex2f(m2 - nm);
                m = nm;
            }
            if (q == 0) {
                int rl = wid * 16 + r * 8 + g4;
                int idx = (rb * NCHUNK + ck) * BM + rl;
                g_pm[idx] = m;
                g_ps[idx] = s;
            }
        }

        // ---- steal next job ----
        if (tid == 0) job_s = atomicAdd(&g_job, 1);
        __syncthreads();
        job = job_s;
    }
}

// ---------------- finalize: merge 8 partials/row ----------------
__global__ void final_kernel(const float* __restrict__ X, float* __restrict__ out) {
    int r = blockIdx.x * blockDim.x + threadIdx.x;
    if (r >= N_SRC) return;
    int rb = r >> 7, rl = r & 127;
    const float invmv = g_scalars[0];
    const float mpsi  = g_scalars[2];
    float m = -INFINITY, s = 0.f;
#pragma unroll
    for (int ck = 0; ck < NCHUNK; ck++) {
        int idx = (rb * NCHUNK + ck) * BM + rl;
        float m2 = g_pm[idx], s2v = g_ps[idx];
        float nm = fmaxf(m, m2);
        s = s * ex2f(m - nm) + s2v * ex2f(m2 - nm);
        m = nm;
    }
    const float4* xr = reinterpret_cast<const float4*>(X + (size_t)r * D_DIM);
    float xs = 0.f;
#pragma unroll
    for (int i = 0; i < 16; i++) {
        float4 v = xr[i];
        xs = fmaf(v.x, v.x, fmaf(v.y, v.y, fmaf(v.z, v.z, fmaf(v.w, v.w, xs))));
    }
    out[r] = fmaf(xs, invmv, mpsi) - (REG_P * LN2) * (m + lg2f(s));
}

// ---------------- launch ----------------
extern "C" void kernel_launch(void* const* d_in, const int* in_sizes, int n_in,
                              void* d_out, int out_size) {
    const float *X = nullptr, *Y = nullptr, *psi = nullptr;
    for (int i = 0; i < n_in; i++) {
        if (in_sizes[i] == N_SRC * D_DIM)      X   = (const float*)d_in[i];
        else if (in_sizes[i] == M_TGT * D_DIM) Y   = (const float*)d_in[i];
        else if (in_sizes[i] == M_TGT)         psi = (const float*)d_in[i];
    }
    float* out = (float*)d_out;

    convX_kernel<<<(N_SRC * D_DIM / 2 + 255) / 256, 256>>>(X);
    convY_tysq_kernel<<<(M_TGT * 8) / 256, 256>>>(Y);
    prep_kernel<<<1, 1024>>>(psi);

    cudaFuncSetAttribute(lse_mma_kernel,
                         cudaFuncAttributeMaxDynamicSharedMemorySize, SM_TOTAL);
    lse_mma_kernel<<<GRID, NT, SM_TOTAL>>>();

    final_kernel<<<N_SRC / 256, 256>>>(X, out);
}

// round 17
// speedup vs baseline: 1.2367x; 1.0518x over previous
#include <cuda_runtime.h>
#include <cuda_fp16.h>
#include <math.h>
#include <cstdint>

#define N_SRC 32768
#define M_TGT 8192
#define D_DIM 64
#define REG_P 0.01f
#define INV_REG 100.0f
#define LOG2E 1.4426950408889634f
#define LN2 0.6931471805599453f

#define BM 128
#define BN 64
#define NT 256
#define NCPSM 4
#define GRID (148 * NCPSM)      // 592
#define NRB (N_SRC / BM)        // 256 row-blocks
#define NCHUNK 4
#define TPC 32                  // 64-row tiles per chunk
#define NPAIR (TPC / 2)         // 16
#define NJOBS (NRB * NCHUNK)    // 1024
#define NSTAGE 4

// ---------------- scratch ----------------
__device__ float  g_tysq[M_TGT];
__device__ float  g_c2[M_TGT];
__device__ float  g_scalars[4];      // 0: 1/mv, 1: 2*invmv*INV_REG*LOG2E, 2: mean(psi)
__device__ __half g_Xh[N_SRC * D_DIM];
__device__ __half g_Yh[M_TGT * D_DIM];
__device__ float  g_pm[NRB * NCHUNK * BM];   // [rb][ck][row]
__device__ float  g_ps[NRB * NCHUNK * BM];
__device__ int    g_job;

// ---------------- helpers ----------------
__device__ __forceinline__ uint32_t smem_u32(const void* p) {
    uint32_t a;
    asm("{ .reg .u64 t; cvta.to.shared.u64 t, %1; cvt.u32.u64 %0, t; }" : "=r"(a) : "l"(p));
    return a;
}
__device__ __forceinline__ uint64_t gmem_u64(const void* p) {
    uint64_t a;
    asm("cvta.to.global.u64 %0, %1;" : "=l"(a) : "l"(p));
    return a;
}
__device__ __forceinline__ float ex2f(float x) {
    float r; asm("ex2.approx.ftz.f32 %0, %1;" : "=f"(r) : "f"(x)); return r;
}
__device__ __forceinline__ float lg2f(float x) {
    float r; asm("lg2.approx.f32 %0, %1;" : "=f"(r) : "f"(x)); return r;
}

#define CP_ASYNC16(s, g) \
    asm volatile("cp.async.cg.shared.global [%0], [%1], 16;" :: "r"(s), "l"(g))
#define CP_COMMIT() asm volatile("cp.async.commit_group;" ::: "memory")
#define CP_WAIT(n)  asm volatile("cp.async.wait_group %0;" :: "n"(n) : "memory")

__device__ __forceinline__ void ldsm4(uint32_t* r, uint32_t addr) {
    asm volatile("ldmatrix.sync.aligned.m8n8.x4.shared.b16 {%0,%1,%2,%3}, [%4];"
                 : "=r"(r[0]), "=r"(r[1]), "=r"(r[2]), "=r"(r[3]) : "r"(addr));
}
__device__ __forceinline__ void mma_f16(float* c, const uint32_t* a,
                                        uint32_t b0, uint32_t b1) {
    asm volatile("mma.sync.aligned.m16n8k16.row.col.f32.f16.f16.f32 "
                 "{%0,%1,%2,%3}, {%4,%5,%6,%7}, {%8,%9}, {%0,%1,%2,%3};"
                 : "+f"(c[0]), "+f"(c[1]), "+f"(c[2]), "+f"(c[3])
                 : "r"(a[0]), "r"(a[1]), "r"(a[2]), "r"(a[3]), "r"(b0), "r"(b1));
}
__device__ __forceinline__ void mma_f16_dc(float* d, const uint32_t* a,
                                           uint32_t b0, uint32_t b1,
                                           const float* c) {
    asm volatile("mma.sync.aligned.m16n8k16.row.col.f32.f16.f16.f32 "
                 "{%0,%1,%2,%3}, {%4,%5,%6,%7}, {%8,%9}, {%10,%11,%12,%13};"
                 : "=f"(d[0]), "=f"(d[1]), "=f"(d[2]), "=f"(d[3])
                 : "r"(a[0]), "r"(a[1]), "r"(a[2]), "r"(a[3]), "r"(b0), "r"(b1),
                   "f"(c[0]), "f"(c[1]), "f"(c[2]), "f"(c[3]));
}

// smem layout (bytes): Xh 16KB | Yh 4x8KB | cs 4x256B
#define SM_X 0
#define SM_Y 16384
#define SM_C (16384 + NSTAGE * 8192)
#define SM_TOTAL (SM_C + NSTAGE * 256 + 128)   // ~50.3 KB; x4 CTAs fits

// ---------------- prologue kernels ----------------
__global__ void convX_kernel(const float* __restrict__ src) {
    int i = blockIdx.x * blockDim.x + threadIdx.x;
    if (i >= N_SRC * D_DIM / 2) return;
    float2 v = reinterpret_cast<const float2*>(src)[i];
    reinterpret_cast<__half2*>(g_Xh)[i] = __float22half2_rn(v);
}

__global__ void convY_tysq_kernel(const float* __restrict__ Y) {
    int gid = blockIdx.x * blockDim.x + threadIdx.x;
    int r = gid >> 3, c8 = gid & 7;
    const float4* p = reinterpret_cast<const float4*>(Y + (size_t)r * D_DIM + c8 * 8);
    float4 v0 = p[0], v1 = p[1];
    __half2 h[4];
    h[0] = __float22half2_rn(make_float2(v0.x, v0.y));
    h[1] = __float22half2_rn(make_float2(v0.z, v0.w));
    h[2] = __float22half2_rn(make_float2(v1.x, v1.y));
    h[3] = __float22half2_rn(make_float2(v1.z, v1.w));
    *reinterpret_cast<uint4*>(g_Yh + (size_t)r * D_DIM + c8 * 8) =
        *reinterpret_cast<uint4*>(h);
    float s = v0.x * v0.x + v0.y * v0.y + v0.z * v0.z + v0.w * v0.w
            + v1.x * v1.x + v1.y * v1.y + v1.z * v1.z + v1.w * v1.w;
    s += __shfl_down_sync(0xffffffffu, s, 4, 8);
    s += __shfl_down_sync(0xffffffffu, s, 2, 8);
    s += __shfl_down_sync(0xffffffffu, s, 1, 8);
    if (c8 == 0) g_tysq[r] = s;
}

__global__ void prep_kernel(const float* __restrict__ psi) {
    __shared__ float red_t[1024];
    __shared__ float red_p[1024];
    __shared__ float inv_mv_s;
    int t = threadIdx.x;
    float st = 0.f, sp = 0.f;
    for (int m = t; m < M_TGT; m += 1024) { st += g_tysq[m]; sp += psi[m]; }
    red_t[t] = st; red_p[t] = sp;
    __syncthreads();
    for (int off = 512; off > 0; off >>= 1) {
        if (t < off) { red_t[t] += red_t[t + off]; red_p[t] += red_p[t + off]; }
        __syncthreads();
    }
    if (t == 0) {
        float mv = red_t[0] / (float)M_TGT;
        float inv_mv = 1.0f / mv;
        g_scalars[0] = inv_mv;
        g_scalars[1] = 2.0f * inv_mv * INV_REG * LOG2E;
        g_scalars[2] = red_p[0] / (float)M_TGT;
        inv_mv_s = inv_mv;
        g_job = GRID;
    }
    __syncthreads();
    float inv_mv = inv_mv_s;
    for (int m = t; m < M_TGT; m += 1024)
        g_c2[m] = (psi[m] - g_tysq[m] * inv_mv) * (INV_REG * LOG2E);
}

// ---------------- main kernel: 8 warps x 16-row tiles, 4 CTAs/SM ----------
extern __shared__ char smem[];

__device__ __forceinline__ void prefetch_pair(uint32_t sb, uint64_t Yg, uint64_t Cg,
                                              int gt0, int sbase_idx, int tid) {
    // pair: tiles gt0, gt0+1 -> stages sbase_idx, sbase_idx+1
#pragma unroll
    for (int tt = 0; tt < 2; tt++) {
        uint64_t gb = Yg + (uint64_t)(gt0 + tt) * 8192;
        uint32_t sbase = sb + SM_Y + (sbase_idx + tt) * 8192;
#pragma unroll
        for (int i = 0; i < 2; i++) {
            int idx = tid + i * NT;
            int row = idx >> 3, ch = idx & 7;
            CP_ASYNC16(sbase + row * 128 + ((ch ^ (row & 7)) << 4),
                       gb + row * 128 + ch * 16);
        }
    }
    if (tid < 32) {
        int tt = tid >> 4, l = tid & 15;
        CP_ASYNC16(sb + SM_C + (sbase_idx + tt) * 256 + l * 16,
                   Cg + (uint64_t)(gt0 + tt) * 256 + l * 16);
    }
}

__global__ __launch_bounds__(NT, NCPSM)
void lse_mma_kernel() {
    __shared__ int job_s;
    const uint32_t sb = smem_u32(smem);
    const int tid  = threadIdx.x;
    const int lane = tid & 31;
    const int wid  = tid >> 5;           // row group: rows wid*16..+15
    const int q  = lane & 3;
    const int g4 = lane >> 2;

    const float s2 = g_scalars[1];

    const uint64_t Yg = gmem_u64(g_Yh);
    const uint64_t Cg = gmem_u64(g_c2);

    const int b = lane >> 3, lr = lane & 7;
    const int rselA = (b & 1) * 8, cselA = b >> 1;
    const int rselB = (b >> 1) * 8, cselB = b & 1;

    float zc[4];
#pragma unroll
    for (int j = 0; j < 4; j++) zc[j] = 0.f;

    uint32_t boff[4];
#pragma unroll
    for (int ks = 0; ks < 4; ks++)
        boff[ks] = (uint32_t)(((ks * 2 + cselB) ^ lr) << 4);

    int job = blockIdx.x;
    while (job < NJOBS) {
        const int rb = job >> 2;
        const int ck = job & 3;
        const int rowBase = rb * BM;
        const int tile0 = ck * TPC;

        // ---- X tile (fp16, 128 rows) -> smem ----
#pragma unroll
        for (int i = 0; i < 4; i++) {
            int idx = tid + i * NT;
            int row = idx >> 3, ch = idx & 7;
            uint4 v = *reinterpret_cast<const uint4*>(
                reinterpret_cast<const char*>(g_Xh) +
                (uint64_t)(rowBase + row) * 128 + ch * 16);
            *reinterpret_cast<uint4*>(smem + SM_X + row * 128 +
                                      ((ch ^ (row & 7)) << 4)) = v;
        }
        // ---- prefetch pair 0 (tiles 0,1 -> stages 0,1) ----
        prefetch_pair(sb, Yg, Cg, tile0, 0, tid);
        CP_COMMIT();
        __syncthreads();

        // ---- A fragments (persistent, 16 rows): 16 regs, 4 ldsm ----
        uint32_t A[4][4];
#pragma unroll
        for (int ks = 0; ks < 4; ks++) {
            int row = wid * 16 + rselA + lr;
            int ch  = ks * 2 + cselA;
            ldsm4(A[ks], sb + SM_X + row * 128 + ((ch ^ lr) << 4));
        }

        float runm[2], runs[2];      // row g4, row g4+8
        runm[0] = runm[1] = -INFINITY;
        runs[0] = runs[1] = 0.f;

        for (int p = 0; p < NPAIR; p++) {
            CP_WAIT(0);            // pair p arrived (sole pending group)
            __syncthreads();       // all warps done with pair p-1's stages
            const int sb0 = (p & 1) * 2;      // stages of this pair

            // prefetch pair p+1 into pair p-1's stages (free after the sync)
            if (p + 1 < NPAIR) {
                prefetch_pair(sb, Yg, Cg, tile0 + (p + 1) * 2,
                              ((p + 1) & 1) * 2, tid);
                CP_COMMIT();
            }

#pragma unroll
            for (int tt = 0; tt < 2; tt++) {
                const int buf = sb0 + tt;
                const uint32_t yb = sb + SM_Y + buf * 8192;

#pragma unroll
                for (int nt4 = 0; nt4 < 4; nt4++) {       // 16-col groups
                    const uint32_t rowb =
                        yb + (uint32_t)(nt4 * 16 + rselB + lr) * 128;
                    float2 cp0, cp1;
                    {
                        const float* cbB =
                            reinterpret_cast<const float*>(smem + SM_C + buf * 256)
                            + nt4 * 16;
                        cp0 = *reinterpret_cast<const float2*>(cbB + q * 2);
                        cp1 = *reinterpret_cast<const float2*>(cbB + 8 + q * 2);
                    }

                    float acc[2][4];
                    uint32_t Ba[4], Bb[4];
                    ldsm4(Ba, rowb + boff[0]);
                    ldsm4(Bb, rowb + boff[1]);
                    mma_f16_dc(acc[0], A[0], Ba[0], Ba[1], zc);
                    mma_f16_dc(acc[1], A[0], Ba[2], Ba[3], zc);
                    ldsm4(Ba, rowb + boff[2]);
                    mma_f16(acc[0], A[1], Bb[0], Bb[1]);
                    mma_f16(acc[1], A[1], Bb[2], Bb[3]);
                    ldsm4(Bb, rowb + boff[3]);
                    mma_f16(acc[0], A[2], Ba[0], Ba[1]);
                    mma_f16(acc[1], A[2], Ba[2], Ba[3]);
                    mma_f16(acc[0], A[3], Bb[0], Bb[1]);
                    mma_f16(acc[1], A[3], Bb[2], Bb[3]);

                    // epilogue: v = c + s2*dot; one prune region per nt4
                    float v00 = fmaf(s2, acc[0][0], cp0.x);
                    float v01 = fmaf(s2, acc[0][1], cp0.y);
                    float v02 = fmaf(s2, acc[1][0], cp1.x);
                    float v03 = fmaf(s2, acc[1][1], cp1.y);
                    float v10 = fmaf(s2, acc[0][2], cp0.x);
                    float v11 = fmaf(s2, acc[0][3], cp0.y);
                    float v12 = fmaf(s2, acc[1][2], cp1.x);
                    float v13 = fmaf(s2, acc[1][3], cp1.y);
                    float mx0 = fmaxf(fmaxf(v00, v01), fmaxf(v02, v03));
                    float mx1 = fmaxf(fmaxf(v10, v11), fmaxf(v12, v13));
                    if (fmaxf(mx0, mx1) > fminf(runm[0], runm[1]) - 15.f) {
                        float nm0 = fmaxf(runm[0], mx0);
                        float nm1 = fmaxf(runm[1], mx1);
                        runs[0] = runs[0] * ex2f(runm[0] - nm0)
                                + ((ex2f(v00 - nm0) + ex2f(v01 - nm0))
                                 + (ex2f(v02 - nm0) + ex2f(v03 - nm0)));
                        runs[1] = runs[1] * ex2f(runm[1] - nm1)
                                + ((ex2f(v10 - nm1) + ex2f(v11 - nm1))
                                 + (ex2f(v12 - nm1) + ex2f(v13 - nm1)));
                        runm[0] = nm0;
                        runm[1] = nm1;
                    }
                }
            }
        }

        // ---- merge across 4 q-lanes per row; write partials ----
#pragma unroll
        for (int r = 0; r < 2; r++) {
            float m = runm[r], s = runs[r];
#pragma unroll
            for (int off = 1; off < 4; off <<= 1) {
                float m2 = __shfl_xor_sync(0xffffffffu, m, off);
                float s2x = __shfl_xor_sync(0xffffffffu, s, off);
                float nm = fmaxf(m, m2);
                s = s * ex2f(m - nm) + s2x * ex2f(m2 - nm);
                m = nm;
            }
            if (q == 0) {
                int rl = wid * 16 + r * 8 + g4;
                int idx = (rb * NCHUNK + ck) * BM + rl;
                g_pm[idx] = m;
                g_ps[idx] = s;
            }
        }

        // ---- steal next job ----
        if (tid == 0) job_s = atomicAdd(&g_job, 1);
        __syncthreads();
        job = job_s;
    }
}

// ---------------- finalize: merge 4 partials/row ----------------
__global__ void final_kernel(const float* __restrict__ X, float* __restrict__ out) {
    int r = blockIdx.x * blockDim.x + threadIdx.x;
    if (r >= N_SRC) return;
    int rb = r >> 7, rl = r & 127;
    const float invmv = g_scalars[0];
    const float mpsi  = g_scalars[2];
    float m = -INFINITY, s = 0.f;
#pragma unroll
    for (int ck = 0; ck < NCHUNK; ck++) {
        int idx = (rb * NCHUNK + ck) * BM + rl;
        float m2 = g_pm[idx], s2v = g_ps[idx];
        float nm = fmaxf(m, m2);
        s = s * ex2f(m - nm) + s2v * ex2f(m2 - nm);
        m = nm;
    }
    const float4* xr = reinterpret_cast<const float4*>(X + (size_t)r * D_DIM);
    float xs = 0.f;
#pragma unroll
    for (int i = 0; i < 16; i++) {
        float4 v = xr[i];
        xs = fmaf(v.x, v.x, fmaf(v.y, v.y, fmaf(v.z, v.z, fmaf(v.w, v.w, xs))));
    }
    out[r] = fmaf(xs, invmv, mpsi) - (REG_P * LN2) * (m + lg2f(s));
}

// ---------------- launch ----------------
extern "C" void kernel_launch(void* const* d_in, const int* in_sizes, int n_in,
                              void* d_out, int out_size) {
    const float *X = nullptr, *Y = nullptr, *psi = nullptr;
    for (int i = 0; i < n_in; i++) {
        if (in_sizes[i] == N_SRC * D_DIM)      X   = (const float*)d_in[i];
        else if (in_sizes[i] == M_TGT * D_DIM) Y   = (const float*)d_in[i];
        else if (in_sizes[i] == M_TGT)         psi = (const float*)d_in[i];
    }
    float* out = (float*)d_out;

    convX_kernel<<<(N_SRC * D_DIM / 2 + 255) / 256, 256>>>(X);
    convY_tysq_kernel<<<(M_TGT * 8) / 256, 256>>>(Y);
    prep_kernel<<<1, 1024>>>(psi);

    cudaFuncSetAttribute(lse_mma_kernel,
                         cudaFuncAttributeMaxDynamicSharedMemorySize, SM_TOTAL);
    lse_mma_kernel<<<GRID, NT, SM_TOTAL>>>();

    final_kernel<<<N_SRC / 256, 256>>>(X, out);
}